// round 8
// baseline (speedup 1.0000x reference)
#include <cuda_runtime.h>
#include <cuda_bf16.h>
#include <cstdint>

// ----------------------------------------------------------------------------
// RelationalMultiAggrMP — bf16 split-GEMM (64x64 warp tiles) + cached aggregate
//   P = Xh@Bh + Xh@Bl + Xl@Bh (bf16 split, fp32 accum)
//   packed along K: Abig[M][384] = [Xh | Xh | Xl], BbigT[n][384] = [Bh | Bl | Bh]
// ----------------------------------------------------------------------------

#define N_NODES    50000
#define M_PAD      50048                     // 391 * 128
#define HIDDEN     128
#define MSG        64
#define MSG3       (3 * MSG)                 // 192
#define N_ETYPES   4
#define E_PER_TYPE 100000
#define N_EDGES    (N_ETYPES * E_PER_TYPE)   // 400000
#define NCOLS      (N_ETYPES * 2 * MSG3)     // 1536
#define KTOT       384                       // 3 * HIDDEN
#define DELTA_F    1.1515f
#define SMALL_F    1e-7f

// -------------------- device scratch (static, no allocation) ---------------
__device__ float          g_P[(size_t)N_NODES * NCOLS];   // 307.2 MB
__device__ float          g_B[HIDDEN * NCOLS];            // fp32 re-layout of W
__device__ __nv_bfloat16  g_Ah[(size_t)M_PAD * KTOT];     // 38.4 MB
__device__ __nv_bfloat16  g_Bt[(size_t)NCOLS * KTOT];     // 1.2 MB  [n][k]
__device__ unsigned       g_cnt[N_NODES];
__device__ unsigned       g_off[N_NODES + 1];
__device__ unsigned       g_cur[N_NODES];
__device__ unsigned       g_elist[N_EDGES];
__device__ int            g_is64;

// -------------------- helpers ------------------------------------------------
__device__ __forceinline__ uint32_t smem_u32(const void* p) {
    uint32_t a;
    asm("{ .reg .u64 t; cvta.to.shared.u64 t, %1; cvt.u32.u64 %0, t; }"
        : "=r"(a) : "l"(p));
    return a;
}

__device__ __forceinline__ void cp_async16(uint32_t saddr, const void* gptr) {
    asm volatile("cp.async.cg.shared.global [%0], [%1], 16;"
                 :: "r"(saddr), "l"(gptr));
}

#define CP_COMMIT()  asm volatile("cp.async.commit_group;" ::: "memory")
#define CP_WAIT(n)   asm volatile("cp.async.wait_group %0;" :: "n"(n) : "memory")

#define LDMATRIX_X4(r0, r1, r2, r3, addr) \
    asm volatile("ldmatrix.sync.aligned.m8n8.x4.shared.b16 {%0,%1,%2,%3}, [%4];" \
                 : "=r"(r0), "=r"(r1), "=r"(r2), "=r"(r3) : "r"(addr))

// -------------------- 0) adjacency dtype detection --------------------------
__global__ void detect_kernel(const unsigned* __restrict__ a0) {
    if (threadIdx.x == 0 && blockIdx.x == 0) {
        int all_zero = 1;
        for (int k = 0; k < 128; k++)
            if (a0[2 * k + 1] != 0u) { all_zero = 0; break; }
        g_is64 = all_zero;
    }
}

// -------------------- 1) weight re-layout + zero counters ------------------
__global__ void prep_kernel(const float* __restrict__ W) {
    int idx = blockIdx.x * blockDim.x + threadIdx.x;
    if (idx < HIDDEN * NCOLS) {
        int k    = idx / NCOLS;
        int c    = idx - k * NCOLS;
        int r    = c / (2 * MSG3);
        int rem  = c - r * (2 * MSG3);
        int role = rem / MSG3;
        int m    = rem - role * MSG3;
        g_B[idx] = W[r * (2 * HIDDEN * MSG3) + (role * HIDDEN + k) * MSG3 + m];
    }
    if (idx < N_NODES) g_cnt[idx] = 0u;
}

// -------------------- 1b) bf16 splits ---------------------------------------
__global__ void split_x_kernel(const float* __restrict__ x) {
    int idx = blockIdx.x * blockDim.x + threadIdx.x;   // over M_PAD*128
    if (idx >= M_PAD * HIDDEN) return;
    int r = idx >> 7;
    int k = idx & 127;
    float v = (r < N_NODES) ? x[idx] : 0.f;
    __nv_bfloat16 h  = __float2bfloat16(v);
    __nv_bfloat16 lo = __float2bfloat16(v - __bfloat162float(h));
    size_t base = (size_t)r * KTOT;
    g_Ah[base + k]       = h;
    g_Ah[base + 128 + k] = h;
    g_Ah[base + 256 + k] = lo;
}

__global__ void split_b_kernel() {
    int idx = blockIdx.x * blockDim.x + threadIdx.x;   // over 128*1536
    if (idx >= HIDDEN * NCOLS) return;
    int k = idx / NCOLS;
    int c = idx - k * NCOLS;
    float v = g_B[idx];
    __nv_bfloat16 h  = __float2bfloat16(v);
    __nv_bfloat16 lo = __float2bfloat16(v - __bfloat162float(h));
    size_t base = (size_t)c * KTOT;
    g_Bt[base + k]       = h;    // pairs with Xh
    g_Bt[base + 128 + k] = lo;   // pairs with Xh
    g_Bt[base + 256 + k] = h;    // pairs with Xl
}

// -------------------- 2) bf16 mma GEMM, 64x64 warp tiles ---------------------
// M=50048, N=1536, K=384; CTA tile 128x128x32, 4 warps (2m x 2n), warp 64x64.
#define AS_STRIDE 40
__global__ __launch_bounds__(128)
void mma_gemm_kernel() {
    __shared__ __nv_bfloat16 As[2][128][AS_STRIDE];
    __shared__ __nv_bfloat16 Bs[2][128][AS_STRIDE];

    int bn   = blockIdx.x * 128;
    int bm   = blockIdx.y * 128;
    int tid  = threadIdx.x;
    int wid  = tid >> 5;
    int lane = tid & 31;
    int wm   = (wid >> 1) * 64;    // warp m offset (0/64)
    int wnb  = (wid & 1) * 64;     // warp n offset (0/64)
    int rg   = lane >> 2;          // 0..7
    int tq   = (lane & 3) * 2;     // 0,2,4,6

    // ldmatrix per-thread byte offsets (within one buffer)
    uint32_t aRowOff = (uint32_t)(wm + (lane & 15)) * (AS_STRIDE * 2)
                       + (uint32_t)((lane >> 4) << 3) * 2;
    uint32_t bRowOff = (uint32_t)(wnb + ((lane >> 4) << 3) + (lane & 7)) * (AS_STRIDE * 2)
                       + (uint32_t)(((lane >> 3) & 1) << 3) * 2;

    uint32_t aBase[2] = { smem_u32(&As[0][0][0]), smem_u32(&As[1][0][0]) };
    uint32_t bBase[2] = { smem_u32(&Bs[0][0][0]), smem_u32(&Bs[1][0][0]) };

    float acc[4][8][4];
#pragma unroll
    for (int mi = 0; mi < 4; mi++)
#pragma unroll
        for (int ni = 0; ni < 8; ni++)
#pragma unroll
            for (int j = 0; j < 4; j++) acc[mi][ni][j] = 0.f;

    // fill: 512 int4 chunks per array, 128 threads -> 4 chunks each
    auto fill = [&](int buf, int kt) {
#pragma unroll
        for (int i = 0; i < 4; i++) {
            int q   = tid + i * 128;       // 0..511
            int row = q >> 2;
            int seg = (q & 3) * 8;         // bf16 elems
            cp_async16(aBase[buf] + (uint32_t)(row * AS_STRIDE + seg) * 2,
                       &g_Ah[(size_t)(bm + row) * KTOT + kt + seg]);
            cp_async16(bBase[buf] + (uint32_t)(row * AS_STRIDE + seg) * 2,
                       &g_Bt[(size_t)(bn + row) * KTOT + kt + seg]);
        }
    };

    fill(0, 0);
    CP_COMMIT();

    const int NITER = KTOT / 32;   // 12
    for (int it = 0; it < NITER; it++) {
        int cur = it & 1;
        if (it < NITER - 1) {
            fill(1 - cur, (it + 1) * 32);
            CP_COMMIT();
            CP_WAIT(1);
        } else {
            CP_WAIT(0);
        }
        __syncthreads();

#pragma unroll
        for (int ks = 0; ks < 32; ks += 16) {
            unsigned a[4][4];
#pragma unroll
            for (int mi = 0; mi < 4; mi++) {
                uint32_t addr = aBase[cur] + aRowOff
                              + (uint32_t)(mi * 16 * AS_STRIDE + ks) * 2;
                LDMATRIX_X4(a[mi][0], a[mi][1], a[mi][2], a[mi][3], addr);
            }
            unsigned bfr[4][4];   // pr = 0..3 covers 64 n-cols
#pragma unroll
            for (int pr = 0; pr < 4; pr++) {
                uint32_t addr = bBase[cur] + bRowOff
                              + (uint32_t)(pr * 16 * AS_STRIDE + ks) * 2;
                LDMATRIX_X4(bfr[pr][0], bfr[pr][1], bfr[pr][2], bfr[pr][3], addr);
            }
#pragma unroll
            for (int mi = 0; mi < 4; mi++)
#pragma unroll
                for (int ni = 0; ni < 8; ni++) {
                    unsigned b0 = bfr[ni >> 1][(ni & 1) * 2];
                    unsigned b1 = bfr[ni >> 1][(ni & 1) * 2 + 1];
                    asm volatile(
                        "mma.sync.aligned.m16n8k16.row.col.f32.bf16.bf16.f32 "
                        "{%0,%1,%2,%3}, {%4,%5,%6,%7}, {%8,%9}, {%0,%1,%2,%3};"
                        : "+f"(acc[mi][ni][0]), "+f"(acc[mi][ni][1]),
                          "+f"(acc[mi][ni][2]), "+f"(acc[mi][ni][3])
                        : "r"(a[mi][0]), "r"(a[mi][1]), "r"(a[mi][2]), "r"(a[mi][3]),
                          "r"(b0), "r"(b1));
                }
        }
        __syncthreads();
    }

    // epilogue
#pragma unroll
    for (int mi = 0; mi < 4; mi++) {
#pragma unroll
        for (int ni = 0; ni < 8; ni++) {
            int r0 = bm + wm + mi * 16 + rg;
            int c  = bn + wnb + ni * 8 + tq;
            if (r0 < N_NODES) {
                float2 v = make_float2(acc[mi][ni][0], acc[mi][ni][1]);
                *reinterpret_cast<float2*>(&g_P[(size_t)r0 * NCOLS + c]) = v;
            }
            if (r0 + 8 < N_NODES) {
                float2 v = make_float2(acc[mi][ni][2], acc[mi][ni][3]);
                *reinterpret_cast<float2*>(&g_P[(size_t)(r0 + 8) * NCOLS + c]) = v;
            }
        }
    }
}

// -------------------- edge decode helper ------------------------------------
__device__ __forceinline__ void load_edge(const unsigned* __restrict__ adj,
                                          int e, int is64, int* s, int* t) {
    if (is64) {
        *s = (int)adj[4 * e];
        *t = (int)adj[4 * e + 2];
    } else {
        *s = (int)adj[2 * e];
        *t = (int)adj[2 * e + 1];
    }
}

// -------------------- 3) per-target degree histogram ------------------------
__global__ void count_kernel(const unsigned* __restrict__ a0,
                             const unsigned* __restrict__ a1,
                             const unsigned* __restrict__ a2,
                             const unsigned* __restrict__ a3) {
    int ge = blockIdx.x * blockDim.x + threadIdx.x;
    if (ge >= N_EDGES) return;
    int r = ge / E_PER_TYPE;
    int e = ge - r * E_PER_TYPE;
    const unsigned* adj = (r == 0) ? a0 : (r == 1) ? a1 : (r == 2) ? a2 : a3;
    int s, t;
    load_edge(adj, e, g_is64, &s, &t);
    if ((unsigned)t < (unsigned)N_NODES)
        atomicAdd(&g_cnt[t], 1u);
}

// -------------------- 4) exclusive scan (single block) ----------------------
__global__ void scan_kernel() {
    __shared__ unsigned sm[1024];
    int tid = threadIdx.x;
    const int CH = (N_NODES + 1023) / 1024;
    int begin = tid * CH;
    int end   = begin + CH;
    if (end > N_NODES) end = N_NODES;
    unsigned local = 0;
    if (begin < N_NODES)
        for (int i = begin; i < end; i++) local += g_cnt[i];
    sm[tid] = local;
    __syncthreads();
    for (int off = 1; off < 1024; off <<= 1) {
        unsigned v = (tid >= off) ? sm[tid - off] : 0u;
        __syncthreads();
        sm[tid] += v;
        __syncthreads();
    }
    unsigned running = sm[tid] - local;
    if (begin < N_NODES) {
        for (int i = begin; i < end; i++) {
            g_off[i] = running;
            g_cur[i] = running;
            running += g_cnt[i];
        }
        if (end == N_NODES) g_off[N_NODES] = running;
    }
}

// -------------------- 5) scatter edge ids into CSR buckets ------------------
__global__ void scatter_kernel(const unsigned* __restrict__ a0,
                               const unsigned* __restrict__ a1,
                               const unsigned* __restrict__ a2,
                               const unsigned* __restrict__ a3) {
    int ge = blockIdx.x * blockDim.x + threadIdx.x;
    if (ge >= N_EDGES) return;
    int r = ge / E_PER_TYPE;
    int e = ge - r * E_PER_TYPE;
    const unsigned* adj = (r == 0) ? a0 : (r == 1) ? a1 : (r == 2) ? a2 : a3;
    int s, t;
    load_edge(adj, e, g_is64, &s, &t);
    if ((unsigned)t >= (unsigned)N_NODES || (unsigned)s >= (unsigned)N_NODES)
        return;
    unsigned pos = atomicAdd(&g_cur[t], 1u);
    if (pos < (unsigned)N_EDGES)
        g_elist[pos] = ((unsigned)s << 2) | (unsigned)r;
}

// -------------------- 6) warp-per-node aggregate + finalize -----------------
// smem cache of mean-slice messages (first CAP edges per node) kills the
// pass-2 random re-gather for >99% of edges.
#define CAP 16
__global__ __launch_bounds__(256)
void aggregate_kernel(const float* __restrict__ b, float* __restrict__ out) {
    __shared__ float cache[8][CAP * 64];   // 32 KB

    int widx = threadIdx.x >> 5;
    int gw   = (blockIdx.x * blockDim.x + threadIdx.x) >> 5;
    int lane = threadIdx.x & 31;
    if (gw >= N_NODES) return;
    int v = gw;
    unsigned beg = g_off[v], end = g_off[v + 1];
    float cnt = (float)(end - beg);

    const float* Pv = g_P + (size_t)v * NCOLS;
    float* mc = cache[widx];

    float asum[2]  = {0.f, 0.f};
    float amean[2] = {0.f, 0.f};
    float amax[2]  = {0.f, 0.f};

    for (unsigned p = beg; p < end; p++) {
        unsigned pk = g_elist[p];
        int s = (int)(pk >> 2);
        int r = (int)(pk & 3u);
        const float* Ps = g_P + (size_t)s * NCOLS + r * (2 * MSG3);
        const float* Pt = Pv + r * (2 * MSG3) + MSG3;
        const float* bb = b + r * MSG3;
        unsigned i = p - beg;
#pragma unroll
        for (int g = 0; g < 2; g++) {
            int c = g * 32 + lane;
            float m0 = fmaxf(Ps[c]       + Pt[c]       + __ldg(&bb[c]),       0.f);
            float m1 = fmaxf(Ps[64 + c]  + Pt[64 + c]  + __ldg(&bb[64 + c]),  0.f);
            float m2 = fmaxf(Ps[128 + c] + Pt[128 + c] + __ldg(&bb[128 + c]), 0.f);
            asum[g]  += m0;
            amean[g] += m1;
            amax[g]   = fmaxf(amax[g], m2);
            if (i < CAP) mc[i * 64 + c] = m1;
        }
    }

    float denom = fmaxf(cnt, 1.f);
    float meanv[2] = {amean[0] / denom, amean[1] / denom};

    // variance pass: cached mean-slice messages; fallback gather beyond CAP
    float avar[2] = {0.f, 0.f};
    for (unsigned p = beg; p < end; p++) {
        unsigned i = p - beg;
        if (i < CAP) {
#pragma unroll
            for (int g = 0; g < 2; g++) {
                int c = g * 32 + lane;
                float m = mc[i * 64 + c];
                avar[g] += fmaxf(m * m - meanv[g] * meanv[g], 0.f) + SMALL_F;
            }
        } else {
            unsigned pk = g_elist[p];
            int s = (int)(pk >> 2);
            int r = (int)(pk & 3u);
            const float* Ps = g_P + (size_t)s * NCOLS + r * (2 * MSG3);
            const float* Pt = Pv + r * (2 * MSG3) + MSG3;
            const float* bb = b + r * MSG3;
#pragma unroll
            for (int g = 0; g < 2; g++) {
                int c = 64 + g * 32 + lane;
                float m = fmaxf(Ps[c] + Pt[c] + __ldg(&bb[c]), 0.f);
                avar[g] += fmaxf(m * m - meanv[g] * meanv[g], 0.f) + SMALL_F;
            }
        }
    }

    bool  has = cnt > 0.f;
    float ld  = logf(cnt + 1.f);
    float amp = ld / DELTA_F;
    float att = DELTA_F / (ld + SMALL_F);

    float* o = out + (size_t)v * 768;
#pragma unroll
    for (int g = 0; g < 2; g++) {
        int j = g * 32 + lane;
        float sd = has ? sqrtf(avar[g]) : 0.f;
        float vals[4] = {asum[g], meanv[g], sd, amax[g]};
#pragma unroll
        for (int sct = 0; sct < 4; sct++) {
            float vv = vals[sct];
            o[sct * 64 + j]       = vv;
            o[256 + sct * 64 + j] = amp * vv;
            o[512 + sct * 64 + j] = att * vv;
        }
    }
}

// -------------------- launch ------------------------------------------------
extern "C" void kernel_launch(void* const* d_in, const int* in_sizes, int n_in,
                              void* d_out, int out_size) {
    (void)in_sizes; (void)n_in; (void)out_size;
    const float*    x  = (const float*)d_in[0];
    const unsigned* a0 = (const unsigned*)d_in[1];
    const unsigned* a1 = (const unsigned*)d_in[2];
    const unsigned* a2 = (const unsigned*)d_in[3];
    const unsigned* a3 = (const unsigned*)d_in[4];
    const float*    W  = (const float*)d_in[5];
    const float*    b  = (const float*)d_in[6];
    float*          out = (float*)d_out;

    detect_kernel<<<1, 32>>>(a0);
    prep_kernel<<<(HIDDEN * NCOLS + 255) / 256, 256>>>(W);
    split_b_kernel<<<(HIDDEN * NCOLS + 255) / 256, 256>>>();
    split_x_kernel<<<(M_PAD * HIDDEN + 255) / 256, 256>>>(x);
    mma_gemm_kernel<<<dim3(NCOLS / 128, M_PAD / 128), 128>>>();
    count_kernel<<<(N_EDGES + 255) / 256, 256>>>(a0, a1, a2, a3);
    scan_kernel<<<1, 1024>>>();
    scatter_kernel<<<(N_EDGES + 255) / 256, 256>>>(a0, a1, a2, a3);
    aggregate_kernel<<<(N_NODES * 32 + 255) / 256, 256>>>(b, out);
}

// round 10
// speedup vs baseline: 1.0111x; 1.0111x over previous
#include <cuda_runtime.h>
#include <cuda_bf16.h>
#include <cstdint>

// ----------------------------------------------------------------------------
// RelationalMultiAggrMP — R7 GEMM (8 warps, 64x32 tiles) + cached aggregate
//   P = Xh@Bh + Xh@Bl + Xl@Bh (bf16 split, fp32 accum)
//   packed along K: Abig[M][384] = [Xh | Xh | Xl], BbigT[n][384] = [Bh | Bl | Bh]
// ----------------------------------------------------------------------------

#define N_NODES    50000
#define M_PAD      50048                     // 391 * 128
#define HIDDEN     128
#define MSG        64
#define MSG3       (3 * MSG)                 // 192
#define N_ETYPES   4
#define E_PER_TYPE 100000
#define N_EDGES    (N_ETYPES * E_PER_TYPE)   // 400000
#define NCOLS      (N_ETYPES * 2 * MSG3)     // 1536
#define KTOT       384                       // 3 * HIDDEN
#define DELTA_F    1.1515f
#define SMALL_F    1e-7f

// -------------------- device scratch (static, no allocation) ---------------
__device__ float          g_P[(size_t)N_NODES * NCOLS];   // 307.2 MB
__device__ float          g_B[HIDDEN * NCOLS];            // fp32 re-layout of W
__device__ __nv_bfloat16  g_Ah[(size_t)M_PAD * KTOT];     // 38.4 MB
__device__ __nv_bfloat16  g_Bt[(size_t)NCOLS * KTOT];     // 1.2 MB  [n][k]
__device__ unsigned       g_cnt[N_NODES];
__device__ unsigned       g_off[N_NODES + 1];
__device__ unsigned       g_cur[N_NODES];
__device__ unsigned       g_elist[N_EDGES];
__device__ int            g_is64;

// -------------------- helpers ------------------------------------------------
__device__ __forceinline__ uint32_t smem_u32(const void* p) {
    uint32_t a;
    asm("{ .reg .u64 t; cvta.to.shared.u64 t, %1; cvt.u32.u64 %0, t; }"
        : "=r"(a) : "l"(p));
    return a;
}

__device__ __forceinline__ void cp_async16(uint32_t saddr, const void* gptr) {
    asm volatile("cp.async.cg.shared.global [%0], [%1], 16;"
                 :: "r"(saddr), "l"(gptr));
}

#define CP_COMMIT()  asm volatile("cp.async.commit_group;" ::: "memory")
#define CP_WAIT(n)   asm volatile("cp.async.wait_group %0;" :: "n"(n) : "memory")

#define LDMATRIX_X4(r0, r1, r2, r3, addr) \
    asm volatile("ldmatrix.sync.aligned.m8n8.x4.shared.b16 {%0,%1,%2,%3}, [%4];" \
                 : "=r"(r0), "=r"(r1), "=r"(r2), "=r"(r3) : "r"(addr))

// -------------------- 0) adjacency dtype detection --------------------------
__global__ void detect_kernel(const unsigned* __restrict__ a0) {
    if (threadIdx.x == 0 && blockIdx.x == 0) {
        int all_zero = 1;
        for (int k = 0; k < 128; k++)
            if (a0[2 * k + 1] != 0u) { all_zero = 0; break; }
        g_is64 = all_zero;
    }
}

// -------------------- 1) weight re-layout + zero counters ------------------
__global__ void prep_kernel(const float* __restrict__ W) {
    int idx = blockIdx.x * blockDim.x + threadIdx.x;
    if (idx < HIDDEN * NCOLS) {
        int k    = idx / NCOLS;
        int c    = idx - k * NCOLS;
        int r    = c / (2 * MSG3);
        int rem  = c - r * (2 * MSG3);
        int role = rem / MSG3;
        int m    = rem - role * MSG3;
        g_B[idx] = W[r * (2 * HIDDEN * MSG3) + (role * HIDDEN + k) * MSG3 + m];
    }
    if (idx < N_NODES) g_cnt[idx] = 0u;
}

// -------------------- 1b) bf16 splits ---------------------------------------
__global__ void split_x_kernel(const float* __restrict__ x) {
    int idx = blockIdx.x * blockDim.x + threadIdx.x;   // over M_PAD*128
    if (idx >= M_PAD * HIDDEN) return;
    int r = idx >> 7;
    int k = idx & 127;
    float v = (r < N_NODES) ? x[idx] : 0.f;
    __nv_bfloat16 h  = __float2bfloat16(v);
    __nv_bfloat16 lo = __float2bfloat16(v - __bfloat162float(h));
    size_t base = (size_t)r * KTOT;
    g_Ah[base + k]       = h;
    g_Ah[base + 128 + k] = h;
    g_Ah[base + 256 + k] = lo;
}

__global__ void split_b_kernel() {
    int idx = blockIdx.x * blockDim.x + threadIdx.x;   // over 128*1536
    if (idx >= HIDDEN * NCOLS) return;
    int k = idx / NCOLS;
    int c = idx - k * NCOLS;
    float v = g_B[idx];
    __nv_bfloat16 h  = __float2bfloat16(v);
    __nv_bfloat16 lo = __float2bfloat16(v - __bfloat162float(h));
    size_t base = (size_t)c * KTOT;
    g_Bt[base + k]       = h;    // pairs with Xh
    g_Bt[base + 128 + k] = lo;   // pairs with Xh
    g_Bt[base + 256 + k] = h;    // pairs with Xl
}

// -------------------- 2) bf16 mma GEMM, ldmatrix + cp.async (R7 config) ------
// M=50048, N=1536, K=384; CTA tile 128x128x32, 8 warps (2m x 4n), warp 64x32.
#define AS_STRIDE 40
__global__ __launch_bounds__(256, 2)
void mma_gemm_kernel() {
    __shared__ __nv_bfloat16 As[2][128][AS_STRIDE];
    __shared__ __nv_bfloat16 Bs[2][128][AS_STRIDE];

    int bn   = blockIdx.x * 128;
    int bm   = blockIdx.y * 128;
    int tid  = threadIdx.x;
    int wid  = tid >> 5;
    int lane = tid & 31;
    int wm   = (wid >> 2) * 64;    // warp m offset (0/64)
    int wnb  = (wid & 3) * 32;     // warp n offset (0/32/64/96)
    int rg   = lane >> 2;          // 0..7
    int tq   = (lane & 3) * 2;     // 0,2,4,6

    uint32_t aRowOff = (uint32_t)(wm + (lane & 15)) * (AS_STRIDE * 2)
                       + (uint32_t)((lane >> 4) << 3) * 2;
    uint32_t bRowOff = (uint32_t)(wnb + ((lane >> 4) << 3) + (lane & 7)) * (AS_STRIDE * 2)
                       + (uint32_t)(((lane >> 3) & 1) << 3) * 2;

    uint32_t aBase[2] = { smem_u32(&As[0][0][0]), smem_u32(&As[1][0][0]) };
    uint32_t bBase[2] = { smem_u32(&Bs[0][0][0]), smem_u32(&Bs[1][0][0]) };

    float acc[4][4][4];
#pragma unroll
    for (int mi = 0; mi < 4; mi++)
#pragma unroll
        for (int ni = 0; ni < 4; ni++)
#pragma unroll
            for (int j = 0; j < 4; j++) acc[mi][ni][j] = 0.f;

    auto fill = [&](int buf, int kt) {
#pragma unroll
        for (int i = 0; i < 2; i++) {
            int q   = tid + i * 256;       // 0..511
            int row = q >> 2;
            int seg = (q & 3) * 8;         // bf16 elems
            cp_async16(aBase[buf] + (uint32_t)(row * AS_STRIDE + seg) * 2,
                       &g_Ah[(size_t)(bm + row) * KTOT + kt + seg]);
            cp_async16(bBase[buf] + (uint32_t)(row * AS_STRIDE + seg) * 2,
                       &g_Bt[(size_t)(bn + row) * KTOT + kt + seg]);
        }
    };

    fill(0, 0);
    CP_COMMIT();

    const int NITER = KTOT / 32;   // 12
    for (int it = 0; it < NITER; it++) {
        int cur = it & 1;
        if (it < NITER - 1) {
            fill(1 - cur, (it + 1) * 32);
            CP_COMMIT();
            CP_WAIT(1);
        } else {
            CP_WAIT(0);
        }
        __syncthreads();

#pragma unroll
        for (int ks = 0; ks < 32; ks += 16) {
            unsigned a[4][4];
#pragma unroll
            for (int mi = 0; mi < 4; mi++) {
                uint32_t addr = aBase[cur] + aRowOff
                              + (uint32_t)(mi * 16 * AS_STRIDE + ks) * 2;
                LDMATRIX_X4(a[mi][0], a[mi][1], a[mi][2], a[mi][3], addr);
            }
            unsigned bfr[2][4];
#pragma unroll
            for (int pr = 0; pr < 2; pr++) {
                uint32_t addr = bBase[cur] + bRowOff
                              + (uint32_t)(pr * 16 * AS_STRIDE + ks) * 2;
                LDMATRIX_X4(bfr[pr][0], bfr[pr][1], bfr[pr][2], bfr[pr][3], addr);
            }
#pragma unroll
            for (int mi = 0; mi < 4; mi++)
#pragma unroll
                for (int ni = 0; ni < 4; ni++) {
                    unsigned b0 = bfr[ni >> 1][(ni & 1) * 2];
                    unsigned b1 = bfr[ni >> 1][(ni & 1) * 2 + 1];
                    asm volatile(
                        "mma.sync.aligned.m16n8k16.row.col.f32.bf16.bf16.f32 "
                        "{%0,%1,%2,%3}, {%4,%5,%6,%7}, {%8,%9}, {%0,%1,%2,%3};"
                        : "+f"(acc[mi][ni][0]), "+f"(acc[mi][ni][1]),
                          "+f"(acc[mi][ni][2]), "+f"(acc[mi][ni][3])
                        : "r"(a[mi][0]), "r"(a[mi][1]), "r"(a[mi][2]), "r"(a[mi][3]),
                          "r"(b0), "r"(b1));
                }
        }
        __syncthreads();
    }

    // epilogue
#pragma unroll
    for (int mi = 0; mi < 4; mi++) {
#pragma unroll
        for (int ni = 0; ni < 4; ni++) {
            int r0 = bm + wm + mi * 16 + rg;
            int c  = bn + wnb + ni * 8 + tq;
            if (r0 < N_NODES) {
                float2 v = make_float2(acc[mi][ni][0], acc[mi][ni][1]);
                *reinterpret_cast<float2*>(&g_P[(size_t)r0 * NCOLS + c]) = v;
            }
            if (r0 + 8 < N_NODES) {
                float2 v = make_float2(acc[mi][ni][2], acc[mi][ni][3]);
                *reinterpret_cast<float2*>(&g_P[(size_t)(r0 + 8) * NCOLS + c]) = v;
            }
        }
    }
}

// -------------------- edge decode helper ------------------------------------
__device__ __forceinline__ void load_edge(const unsigned* __restrict__ adj,
                                          int e, int is64, int* s, int* t) {
    if (is64) {
        *s = (int)adj[4 * e];
        *t = (int)adj[4 * e + 2];
    } else {
        *s = (int)adj[2 * e];
        *t = (int)adj[2 * e + 1];
    }
}

// -------------------- 3) per-target degree histogram ------------------------
__global__ void count_kernel(const unsigned* __restrict__ a0,
                             const unsigned* __restrict__ a1,
                             const unsigned* __restrict__ a2,
                             const unsigned* __restrict__ a3) {
    int ge = blockIdx.x * blockDim.x + threadIdx.x;
    if (ge >= N_EDGES) return;
    int r = ge / E_PER_TYPE;
    int e = ge - r * E_PER_TYPE;
    const unsigned* adj = (r == 0) ? a0 : (r == 1) ? a1 : (r == 2) ? a2 : a3;
    int s, t;
    load_edge(adj, e, g_is64, &s, &t);
    if ((unsigned)t < (unsigned)N_NODES)
        atomicAdd(&g_cnt[t], 1u);
}

// -------------------- 4) exclusive scan (single block) ----------------------
__global__ void scan_kernel() {
    __shared__ unsigned sm[1024];
    int tid = threadIdx.x;
    const int CH = (N_NODES + 1023) / 1024;
    int begin = tid * CH;
    int end   = begin + CH;
    if (end > N_NODES) end = N_NODES;
    unsigned local = 0;
    if (begin < N_NODES)
        for (int i = begin; i < end; i++) local += g_cnt[i];
    sm[tid] = local;
    __syncthreads();
    for (int off = 1; off < 1024; off <<= 1) {
        unsigned v = (tid >= off) ? sm[tid - off] : 0u;
        __syncthreads();
        sm[tid] += v;
        __syncthreads();
    }
    unsigned running = sm[tid] - local;
    if (begin < N_NODES) {
        for (int i = begin; i < end; i++) {
            g_off[i] = running;
            g_cur[i] = running;
            running += g_cnt[i];
        }
        if (end == N_NODES) g_off[N_NODES] = running;
    }
}

// -------------------- 5) scatter edge ids into CSR buckets ------------------
__global__ void scatter_kernel(const unsigned* __restrict__ a0,
                               const unsigned* __restrict__ a1,
                               const unsigned* __restrict__ a2,
                               const unsigned* __restrict__ a3) {
    int ge = blockIdx.x * blockDim.x + threadIdx.x;
    if (ge >= N_EDGES) return;
    int r = ge / E_PER_TYPE;
    int e = ge - r * E_PER_TYPE;
    const unsigned* adj = (r == 0) ? a0 : (r == 1) ? a1 : (r == 2) ? a2 : a3;
    int s, t;
    load_edge(adj, e, g_is64, &s, &t);
    if ((unsigned)t >= (unsigned)N_NODES || (unsigned)s >= (unsigned)N_NODES)
        return;
    unsigned pos = atomicAdd(&g_cur[t], 1u);
    if (pos < (unsigned)N_EDGES)
        g_elist[pos] = ((unsigned)s << 2) | (unsigned)r;
}

// -------------------- 6) warp-per-node aggregate + finalize -----------------
// smem cache of mean-slice messages (first CAP edges per node) kills the
// pass-2 random re-gather for >99% of edges.
#define CAP 16
__global__ __launch_bounds__(256)
void aggregate_kernel(const float* __restrict__ b, float* __restrict__ out) {
    __shared__ float cache[8][CAP * 64];   // 32 KB

    int widx = threadIdx.x >> 5;
    int gw   = (blockIdx.x * blockDim.x + threadIdx.x) >> 5;
    int lane = threadIdx.x & 31;
    if (gw >= N_NODES) return;
    int v = gw;
    unsigned beg = g_off[v], end = g_off[v + 1];
    float cnt = (float)(end - beg);

    const float* Pv = g_P + (size_t)v * NCOLS;
    float* mc = cache[widx];

    float asum[2]  = {0.f, 0.f};
    float amean[2] = {0.f, 0.f};
    float amax[2]  = {0.f, 0.f};

    for (unsigned p = beg; p < end; p++) {
        unsigned pk = g_elist[p];
        int s = (int)(pk >> 2);
        int r = (int)(pk & 3u);
        const float* Ps = g_P + (size_t)s * NCOLS + r * (2 * MSG3);
        const float* Pt = Pv + r * (2 * MSG3) + MSG3;
        const float* bb = b + r * MSG3;
        unsigned i = p - beg;
#pragma unroll
        for (int g = 0; g < 2; g++) {
            int c = g * 32 + lane;
            float m0 = fmaxf(Ps[c]       + Pt[c]       + __ldg(&bb[c]),       0.f);
            float m1 = fmaxf(Ps[64 + c]  + Pt[64 + c]  + __ldg(&bb[64 + c]),  0.f);
            float m2 = fmaxf(Ps[128 + c] + Pt[128 + c] + __ldg(&bb[128 + c]), 0.f);
            asum[g]  += m0;
            amean[g] += m1;
            amax[g]   = fmaxf(amax[g], m2);
            if (i < CAP) mc[i * 64 + c] = m1;
        }
    }

    float denom = fmaxf(cnt, 1.f);
    float meanv[2] = {amean[0] / denom, amean[1] / denom};

    // variance pass: cached mean-slice messages; fallback gather beyond CAP
    float avar[2] = {0.f, 0.f};
    for (unsigned p = beg; p < end; p++) {
        unsigned i = p - beg;
        if (i < CAP) {
#pragma unroll
            for (int g = 0; g < 2; g++) {
                int c = g * 32 + lane;
                float m = mc[i * 64 + c];
                avar[g] += fmaxf(m * m - meanv[g] * meanv[g], 0.f) + SMALL_F;
            }
        } else {
            unsigned pk = g_elist[p];
            int s = (int)(pk >> 2);
            int r = (int)(pk & 3u);
            const float* Ps = g_P + (size_t)s * NCOLS + r * (2 * MSG3);
            const float* Pt = Pv + r * (2 * MSG3) + MSG3;
            const float* bb = b + r * MSG3;
#pragma unroll
            for (int g = 0; g < 2; g++) {
                int c = 64 + g * 32 + lane;
                float m = fmaxf(Ps[c] + Pt[c] + __ldg(&bb[c]), 0.f);
                avar[g] += fmaxf(m * m - meanv[g] * meanv[g], 0.f) + SMALL_F;
            }
        }
    }

    bool  has = cnt > 0.f;
    float ld  = logf(cnt + 1.f);
    float amp = ld / DELTA_F;
    float att = DELTA_F / (ld + SMALL_F);

    float* o = out + (size_t)v * 768;
#pragma unroll
    for (int g = 0; g < 2; g++) {
        int j = g * 32 + lane;
        float sd = has ? sqrtf(avar[g]) : 0.f;
        float vals[4] = {asum[g], meanv[g], sd, amax[g]};
#pragma unroll
        for (int sct = 0; sct < 4; sct++) {
            float vv = vals[sct];
            o[sct * 64 + j]       = vv;
            o[256 + sct * 64 + j] = amp * vv;
            o[512 + sct * 64 + j] = att * vv;
        }
    }
}

// -------------------- launch ------------------------------------------------
extern "C" void kernel_launch(void* const* d_in, const int* in_sizes, int n_in,
                              void* d_out, int out_size) {
    (void)in_sizes; (void)n_in; (void)out_size;
    const float*    x  = (const float*)d_in[0];
    const unsigned* a0 = (const unsigned*)d_in[1];
    const unsigned* a1 = (const unsigned*)d_in[2];
    const unsigned* a2 = (const unsigned*)d_in[3];
    const unsigned* a3 = (const unsigned*)d_in[4];
    const float*    W  = (const float*)d_in[5];
    const float*    b  = (const float*)d_in[6];
    float*          out = (float*)d_out;

    detect_kernel<<<1, 32>>>(a0);
    prep_kernel<<<(HIDDEN * NCOLS + 255) / 256, 256>>>(W);
    split_b_kernel<<<(HIDDEN * NCOLS + 255) / 256, 256>>>();
    split_x_kernel<<<(M_PAD * HIDDEN + 255) / 256, 256>>>(x);
    mma_gemm_kernel<<<dim3(NCOLS / 128, M_PAD / 128), 256>>>();
    count_kernel<<<(N_EDGES + 255) / 256, 256>>>(a0, a1, a2, a3);
    scan_kernel<<<1, 1024>>>();
    scatter_kernel<<<(N_EDGES + 255) / 256, 256>>>(a0, a1, a2, a3);
    aggregate_kernel<<<(N_NODES * 32 + 255) / 256, 256>>>(b, out);
}

// round 11
// speedup vs baseline: 1.1240x; 1.1117x over previous
#include <cuda_runtime.h>
#include <cuda_bf16.h>
#include <cstdint>

// ----------------------------------------------------------------------------
// RelationalMultiAggrMP — R7 GEMM upgraded to 3-stage cp.async; R7 aggregate
//   P = Xh@Bh + Xh@Bl + Xl@Bh (bf16 split, fp32 accum)
//   packed along K: Abig[M][384] = [Xh | Xh | Xl], BbigT[n][384] = [Bh | Bl | Bh]
// ----------------------------------------------------------------------------

#define N_NODES    50000
#define M_PAD      50048                     // 391 * 128
#define HIDDEN     128
#define MSG        64
#define MSG3       (3 * MSG)                 // 192
#define N_ETYPES   4
#define E_PER_TYPE 100000
#define N_EDGES    (N_ETYPES * E_PER_TYPE)   // 400000
#define NCOLS      (N_ETYPES * 2 * MSG3)     // 1536
#define KTOT       384                       // 3 * HIDDEN
#define DELTA_F    1.1515f
#define SMALL_F    1e-7f

// -------------------- device scratch (static, no allocation) ---------------
__device__ float          g_P[(size_t)N_NODES * NCOLS];   // 307.2 MB
__device__ float          g_B[HIDDEN * NCOLS];            // fp32 re-layout of W
__device__ __nv_bfloat16  g_Ah[(size_t)M_PAD * KTOT];     // 38.4 MB
__device__ __nv_bfloat16  g_Bt[(size_t)NCOLS * KTOT];     // 1.2 MB  [n][k]
__device__ unsigned       g_cnt[N_NODES];
__device__ unsigned       g_off[N_NODES + 1];
__device__ unsigned       g_cur[N_NODES];
__device__ unsigned       g_elist[N_EDGES];
__device__ int            g_is64;

// -------------------- helpers ------------------------------------------------
__device__ __forceinline__ uint32_t smem_u32(const void* p) {
    uint32_t a;
    asm("{ .reg .u64 t; cvta.to.shared.u64 t, %1; cvt.u32.u64 %0, t; }"
        : "=r"(a) : "l"(p));
    return a;
}

__device__ __forceinline__ void cp_async16(uint32_t saddr, const void* gptr) {
    asm volatile("cp.async.cg.shared.global [%0], [%1], 16;"
                 :: "r"(saddr), "l"(gptr));
}

#define CP_COMMIT()  asm volatile("cp.async.commit_group;" ::: "memory")
#define CP_WAIT(n)   asm volatile("cp.async.wait_group %0;" :: "n"(n) : "memory")

#define LDMATRIX_X4(r0, r1, r2, r3, addr) \
    asm volatile("ldmatrix.sync.aligned.m8n8.x4.shared.b16 {%0,%1,%2,%3}, [%4];" \
                 : "=r"(r0), "=r"(r1), "=r"(r2), "=r"(r3) : "r"(addr))

// -------------------- 0) adjacency dtype detection --------------------------
__global__ void detect_kernel(const unsigned* __restrict__ a0) {
    if (threadIdx.x == 0 && blockIdx.x == 0) {
        int all_zero = 1;
        for (int k = 0; k < 128; k++)
            if (a0[2 * k + 1] != 0u) { all_zero = 0; break; }
        g_is64 = all_zero;
    }
}

// -------------------- 1) weight re-layout + zero counters ------------------
__global__ void prep_kernel(const float* __restrict__ W) {
    int idx = blockIdx.x * blockDim.x + threadIdx.x;
    if (idx < HIDDEN * NCOLS) {
        int k    = idx / NCOLS;
        int c    = idx - k * NCOLS;
        int r    = c / (2 * MSG3);
        int rem  = c - r * (2 * MSG3);
        int role = rem / MSG3;
        int m    = rem - role * MSG3;
        g_B[idx] = W[r * (2 * HIDDEN * MSG3) + (role * HIDDEN + k) * MSG3 + m];
    }
    if (idx < N_NODES) g_cnt[idx] = 0u;
}

// -------------------- 1b) bf16 splits ---------------------------------------
__global__ void split_x_kernel(const float* __restrict__ x) {
    int idx = blockIdx.x * blockDim.x + threadIdx.x;   // over M_PAD*128
    if (idx >= M_PAD * HIDDEN) return;
    int r = idx >> 7;
    int k = idx & 127;
    float v = (r < N_NODES) ? x[idx] : 0.f;
    __nv_bfloat16 h  = __float2bfloat16(v);
    __nv_bfloat16 lo = __float2bfloat16(v - __bfloat162float(h));
    size_t base = (size_t)r * KTOT;
    g_Ah[base + k]       = h;
    g_Ah[base + 128 + k] = h;
    g_Ah[base + 256 + k] = lo;
}

__global__ void split_b_kernel() {
    int idx = blockIdx.x * blockDim.x + threadIdx.x;   // over 128*1536
    if (idx >= HIDDEN * NCOLS) return;
    int k = idx / NCOLS;
    int c = idx - k * NCOLS;
    float v = g_B[idx];
    __nv_bfloat16 h  = __float2bfloat16(v);
    __nv_bfloat16 lo = __float2bfloat16(v - __bfloat162float(h));
    size_t base = (size_t)c * KTOT;
    g_Bt[base + k]       = h;    // pairs with Xh
    g_Bt[base + 128 + k] = lo;   // pairs with Xh
    g_Bt[base + 256 + k] = h;    // pairs with Xl
}

// -------------------- 2) bf16 mma GEMM, 3-stage cp.async pipeline ------------
// M=50048, N=1536, K=384; CTA tile 128x128x32, 8 warps (2m x 4n), warp 64x32.
// Dynamic smem: 3 stages x (As 10240 B + Bs 10240 B) = 61440 B.
#define AS_STRIDE   40
#define STG_BYTES   (128 * AS_STRIDE * 2)          // 10240
#define BS_BASE     (3 * STG_BYTES)                // 30720
#define GEMM_SMEM   (6 * STG_BYTES)                // 61440

__global__ __launch_bounds__(256, 2)
void mma_gemm_kernel() {
    extern __shared__ __align__(16) char dsm[];
    uint32_t dsmB = smem_u32(dsm);

    int bn   = blockIdx.x * 128;
    int bm   = blockIdx.y * 128;
    int tid  = threadIdx.x;
    int wid  = tid >> 5;
    int lane = tid & 31;
    int wm   = (wid >> 2) * 64;    // warp m offset (0/64)
    int wnb  = (wid & 3) * 32;     // warp n offset (0/32/64/96)
    int rg   = lane >> 2;          // 0..7
    int tq   = (lane & 3) * 2;     // 0,2,4,6

    uint32_t aRowOff = (uint32_t)(wm + (lane & 15)) * (AS_STRIDE * 2)
                       + (uint32_t)((lane >> 4) << 3) * 2;
    uint32_t bRowOff = (uint32_t)(wnb + ((lane >> 4) << 3) + (lane & 7)) * (AS_STRIDE * 2)
                       + (uint32_t)(((lane >> 3) & 1) << 3) * 2;

    float acc[4][4][4];
#pragma unroll
    for (int mi = 0; mi < 4; mi++)
#pragma unroll
        for (int ni = 0; ni < 4; ni++)
#pragma unroll
            for (int j = 0; j < 4; j++) acc[mi][ni][j] = 0.f;

    auto fill = [&](int stg, int kt) {
        uint32_t aB = dsmB + (uint32_t)stg * STG_BYTES;
        uint32_t bB = dsmB + BS_BASE + (uint32_t)stg * STG_BYTES;
#pragma unroll
        for (int i = 0; i < 2; i++) {
            int q   = tid + i * 256;       // 0..511
            int row = q >> 2;
            int seg = (q & 3) * 8;         // bf16 elems
            cp_async16(aB + (uint32_t)(row * AS_STRIDE + seg) * 2,
                       &g_Ah[(size_t)(bm + row) * KTOT + kt + seg]);
            cp_async16(bB + (uint32_t)(row * AS_STRIDE + seg) * 2,
                       &g_Bt[(size_t)(bn + row) * KTOT + kt + seg]);
        }
    };

    fill(0, 0);  CP_COMMIT();
    fill(1, 32); CP_COMMIT();

    const int NITER = KTOT / 32;   // 12
    for (int it = 0; it < NITER; it++) {
        int cur = it % 3;
        CP_WAIT(1);           // stage cur complete (<=1 group still in flight)
        __syncthreads();      // also: everyone done reading stage (it+2)%3 (read at it-1)
        if (it + 2 < NITER) {
            fill((it + 2) % 3, (it + 2) * 32);
            CP_COMMIT();
        }

        uint32_t aBase = dsmB + (uint32_t)cur * STG_BYTES;
        uint32_t bBase = dsmB + BS_BASE + (uint32_t)cur * STG_BYTES;

#pragma unroll
        for (int ks = 0; ks < 32; ks += 16) {
            unsigned a[4][4];
#pragma unroll
            for (int mi = 0; mi < 4; mi++) {
                uint32_t addr = aBase + aRowOff
                              + (uint32_t)(mi * 16 * AS_STRIDE + ks) * 2;
                LDMATRIX_X4(a[mi][0], a[mi][1], a[mi][2], a[mi][3], addr);
            }
            unsigned bfr[2][4];
#pragma unroll
            for (int pr = 0; pr < 2; pr++) {
                uint32_t addr = bBase + bRowOff
                              + (uint32_t)(pr * 16 * AS_STRIDE + ks) * 2;
                LDMATRIX_X4(bfr[pr][0], bfr[pr][1], bfr[pr][2], bfr[pr][3], addr);
            }
#pragma unroll
            for (int mi = 0; mi < 4; mi++)
#pragma unroll
                for (int ni = 0; ni < 4; ni++) {
                    unsigned b0 = bfr[ni >> 1][(ni & 1) * 2];
                    unsigned b1 = bfr[ni >> 1][(ni & 1) * 2 + 1];
                    asm volatile(
                        "mma.sync.aligned.m16n8k16.row.col.f32.bf16.bf16.f32 "
                        "{%0,%1,%2,%3}, {%4,%5,%6,%7}, {%8,%9}, {%0,%1,%2,%3};"
                        : "+f"(acc[mi][ni][0]), "+f"(acc[mi][ni][1]),
                          "+f"(acc[mi][ni][2]), "+f"(acc[mi][ni][3])
                        : "r"(a[mi][0]), "r"(a[mi][1]), "r"(a[mi][2]), "r"(a[mi][3]),
                          "r"(b0), "r"(b1));
                }
        }
    }

    // epilogue
#pragma unroll
    for (int mi = 0; mi < 4; mi++) {
#pragma unroll
        for (int ni = 0; ni < 4; ni++) {
            int r0 = bm + wm + mi * 16 + rg;
            int c  = bn + wnb + ni * 8 + tq;
            if (r0 < N_NODES) {
                float2 v = make_float2(acc[mi][ni][0], acc[mi][ni][1]);
                *reinterpret_cast<float2*>(&g_P[(size_t)r0 * NCOLS + c]) = v;
            }
            if (r0 + 8 < N_NODES) {
                float2 v = make_float2(acc[mi][ni][2], acc[mi][ni][3]);
                *reinterpret_cast<float2*>(&g_P[(size_t)(r0 + 8) * NCOLS + c]) = v;
            }
        }
    }
}

// -------------------- edge decode helper ------------------------------------
__device__ __forceinline__ void load_edge(const unsigned* __restrict__ adj,
                                          int e, int is64, int* s, int* t) {
    if (is64) {
        *s = (int)adj[4 * e];
        *t = (int)adj[4 * e + 2];
    } else {
        *s = (int)adj[2 * e];
        *t = (int)adj[2 * e + 1];
    }
}

// -------------------- 3) per-target degree histogram ------------------------
__global__ void count_kernel(const unsigned* __restrict__ a0,
                             const unsigned* __restrict__ a1,
                             const unsigned* __restrict__ a2,
                             const unsigned* __restrict__ a3) {
    int ge = blockIdx.x * blockDim.x + threadIdx.x;
    if (ge >= N_EDGES) return;
    int r = ge / E_PER_TYPE;
    int e = ge - r * E_PER_TYPE;
    const unsigned* adj = (r == 0) ? a0 : (r == 1) ? a1 : (r == 2) ? a2 : a3;
    int s, t;
    load_edge(adj, e, g_is64, &s, &t);
    if ((unsigned)t < (unsigned)N_NODES)
        atomicAdd(&g_cnt[t], 1u);
}

// -------------------- 4) exclusive scan (single block) ----------------------
__global__ void scan_kernel() {
    __shared__ unsigned sm[1024];
    int tid = threadIdx.x;
    const int CH = (N_NODES + 1023) / 1024;
    int begin = tid * CH;
    int end   = begin + CH;
    if (end > N_NODES) end = N_NODES;
    unsigned local = 0;
    if (begin < N_NODES)
        for (int i = begin; i < end; i++) local += g_cnt[i];
    sm[tid] = local;
    __syncthreads();
    for (int off = 1; off < 1024; off <<= 1) {
        unsigned v = (tid >= off) ? sm[tid - off] : 0u;
        __syncthreads();
        sm[tid] += v;
        __syncthreads();
    }
    unsigned running = sm[tid] - local;
    if (begin < N_NODES) {
        for (int i = begin; i < end; i++) {
            g_off[i] = running;
            g_cur[i] = running;
            running += g_cnt[i];
        }
        if (end == N_NODES) g_off[N_NODES] = running;
    }
}

// -------------------- 5) scatter edge ids into CSR buckets ------------------
__global__ void scatter_kernel(const unsigned* __restrict__ a0,
                               const unsigned* __restrict__ a1,
                               const unsigned* __restrict__ a2,
                               const unsigned* __restrict__ a3) {
    int ge = blockIdx.x * blockDim.x + threadIdx.x;
    if (ge >= N_EDGES) return;
    int r = ge / E_PER_TYPE;
    int e = ge - r * E_PER_TYPE;
    const unsigned* adj = (r == 0) ? a0 : (r == 1) ? a1 : (r == 2) ? a2 : a3;
    int s, t;
    load_edge(adj, e, g_is64, &s, &t);
    if ((unsigned)t >= (unsigned)N_NODES || (unsigned)s >= (unsigned)N_NODES)
        return;
    unsigned pos = atomicAdd(&g_cur[t], 1u);
    if (pos < (unsigned)N_EDGES)
        g_elist[pos] = ((unsigned)s << 2) | (unsigned)r;
}

// -------------------- 6) warp-per-node aggregate + finalize (R7 version) ----
__global__ __launch_bounds__(256)
void aggregate_kernel(const float* __restrict__ b, float* __restrict__ out) {
    int gw   = (blockIdx.x * blockDim.x + threadIdx.x) >> 5;
    int lane = threadIdx.x & 31;
    if (gw >= N_NODES) return;
    int v = gw;
    unsigned beg = g_off[v], end = g_off[v + 1];
    float cnt = (float)(end - beg);

    const float* Pv = g_P + (size_t)v * NCOLS;

    float asum[2]  = {0.f, 0.f};
    float amean[2] = {0.f, 0.f};
    float amax[2]  = {0.f, 0.f};

    for (unsigned p = beg; p < end; p++) {
        unsigned pk = g_elist[p];
        int s = (int)(pk >> 2);
        int r = (int)(pk & 3u);
        const float* Ps = g_P + (size_t)s * NCOLS + r * (2 * MSG3);
        const float* Pt = Pv + r * (2 * MSG3) + MSG3;
        const float* bb = b + r * MSG3;
#pragma unroll
        for (int g = 0; g < 2; g++) {
            int c = g * 32 + lane;
            float m0 = fmaxf(Ps[c]       + Pt[c]       + __ldg(&bb[c]),       0.f);
            float m1 = fmaxf(Ps[64 + c]  + Pt[64 + c]  + __ldg(&bb[64 + c]),  0.f);
            float m2 = fmaxf(Ps[128 + c] + Pt[128 + c] + __ldg(&bb[128 + c]), 0.f);
            asum[g]  += m0;
            amean[g] += m1;
            amax[g]   = fmaxf(amax[g], m2);
        }
    }

    float denom = fmaxf(cnt, 1.f);
    float meanv[2] = {amean[0] / denom, amean[1] / denom};

    float avar[2] = {0.f, 0.f};
    for (unsigned p = beg; p < end; p++) {
        unsigned pk = g_elist[p];
        int s = (int)(pk >> 2);
        int r = (int)(pk & 3u);
        const float* Ps = g_P + (size_t)s * NCOLS + r * (2 * MSG3);
        const float* Pt = Pv + r * (2 * MSG3) + MSG3;
        const float* bb = b + r * MSG3;
#pragma unroll
        for (int g = 0; g < 2; g++) {
            int c = 64 + g * 32 + lane;
            float m = fmaxf(Ps[c] + Pt[c] + __ldg(&bb[c]), 0.f);
            float d = fmaxf(m * m - meanv[g] * meanv[g], 0.f) + SMALL_F;
            avar[g] += d;
        }
    }

    bool  has = cnt > 0.f;
    float ld  = logf(cnt + 1.f);
    float amp = ld / DELTA_F;
    float att = DELTA_F / (ld + SMALL_F);

    float* o = out + (size_t)v * 768;
#pragma unroll
    for (int g = 0; g < 2; g++) {
        int j = g * 32 + lane;
        float sd = has ? sqrtf(avar[g]) : 0.f;
        float vals[4] = {asum[g], meanv[g], sd, amax[g]};
#pragma unroll
        for (int sct = 0; sct < 4; sct++) {
            float vv = vals[sct];
            o[sct * 64 + j]       = vv;
            o[256 + sct * 64 + j] = amp * vv;
            o[512 + sct * 64 + j] = att * vv;
        }
    }
}

// -------------------- launch ------------------------------------------------
// Launch order puts mma_gemm_kernel in the ncu-profiled slot (4th launch).
extern "C" void kernel_launch(void* const* d_in, const int* in_sizes, int n_in,
                              void* d_out, int out_size) {
    (void)in_sizes; (void)n_in; (void)out_size;
    const float*    x  = (const float*)d_in[0];
    const unsigned* a0 = (const unsigned*)d_in[1];
    const unsigned* a1 = (const unsigned*)d_in[2];
    const unsigned* a2 = (const unsigned*)d_in[3];
    const unsigned* a3 = (const unsigned*)d_in[4];
    const float*    W  = (const float*)d_in[5];
    const float*    b  = (const float*)d_in[6];
    float*          out = (float*)d_out;

    cudaFuncSetAttribute(mma_gemm_kernel,
                         cudaFuncAttributeMaxDynamicSharedMemorySize,
                         GEMM_SMEM);

    prep_kernel<<<(HIDDEN * NCOLS + 255) / 256, 256>>>(W);
    split_b_kernel<<<(HIDDEN * NCOLS + 255) / 256, 256>>>();
    split_x_kernel<<<(M_PAD * HIDDEN + 255) / 256, 256>>>(x);
    mma_gemm_kernel<<<dim3(NCOLS / 128, M_PAD / 128), 256, GEMM_SMEM>>>();
    detect_kernel<<<1, 32>>>(a0);
    count_kernel<<<(N_EDGES + 255) / 256, 256>>>(a0, a1, a2, a3);
    scan_kernel<<<1, 1024>>>();
    scatter_kernel<<<(N_EDGES + 255) / 256, 256>>>(a0, a1, a2, a3);
    aggregate_kernel<<<(N_NODES * 32 + 255) / 256, 256>>>(b, out);
}